// round 12
// baseline (speedup 1.0000x reference)
#include <cuda_runtime.h>

// Problem constants (fixed shapes from reference setup_inputs)
#define IN      8192
#define OUT     8192
#define RWORDS  1024            // IN * 4 / 32 packed int32 rows
#define KSPLIT  128             // split-K factor
#define RW      (RWORDS / KSPLIT)   // 8 word-rows per block
#define TPB     128
#define OPT     4               // outputs per thread (one 16B stage slot)
#define OBLK    (TPB * OPT)     // 512 outputs per block
#define OTILES  (OUT / OBLK)    // 16
#define DEPTH   4               // cp.async pipeline depth (rows in flight)

// cp.async 16B: global -> shared, bypassing registers. Deep MLP at zero reg cost.
#define CP_ASYNC16(smem_u32, gptr)                                        \
    asm volatile("cp.async.cg.shared.global [%0], [%1], 16;"              \
                 :: "r"(smem_u32), "l"(gptr))
#define CP_COMMIT() asm volatile("cp.async.commit_group;")
#define CP_WAIT(n)  asm volatile("cp.async.wait_group %0;" :: "n"(n))

// PRMT exponent-splice: bytes [0,0,n,0x43] -> exactly 128.0f + n (one ALU op)
__device__ __forceinline__ unsigned nib2f_bits(unsigned v, unsigned sel) {
    unsigned r;
    asm("prmt.b32 %0, %1, %2, %3;" : "=r"(r) : "r"(v), "n"(0x43000000u), "r"(sel));
    return r;
}

// Packed f32x2 FMA: accp += {lo,hi} * xp   (exact fp32 math, 2 MACs/inst)
__device__ __forceinline__ void fma2(unsigned long long& accp,
                                     unsigned lo, unsigned hi,
                                     unsigned long long xp) {
    unsigned long long wp;
    asm("mov.b64 %0, {%1,%2};" : "=l"(wp) : "r"(lo), "r"(hi));
    asm("fma.rn.f32x2 %0, %1, %2, %3;" : "=l"(accp) : "l"(wp), "l"(xp), "l"(accp));
}

// One packed word: 8 nibbles as 4 even/odd k-pairs into an f32x2 accumulator.
__device__ __forceinline__ void proc_word2(unsigned qword, unsigned long long& accp,
                                           const unsigned long long* xp) {
    unsigned wl = qword & 0x0F0F0F0Fu;
    unsigned wh = (qword >> 4) & 0x0F0F0F0Fu;
    fma2(accp, nib2f_bits(wl, 0x7044u), nib2f_bits(wh, 0x7044u), xp[0]);
    fma2(accp, nib2f_bits(wl, 0x7144u), nib2f_bits(wh, 0x7144u), xp[1]);
    fma2(accp, nib2f_bits(wl, 0x7244u), nib2f_bits(wh, 0x7244u), xp[2]);
    fma2(accp, nib2f_bits(wl, 0x7344u), nib2f_bits(wh, 0x7344u), xp[3]);
}

__device__ __forceinline__ float unpack_add(unsigned long long p) {
    unsigned lo, hi;
    asm("mov.b64 {%0,%1}, %2;" : "=r"(lo), "=r"(hi) : "l"(p));
    return __uint_as_float(lo) + __uint_as_float(hi);
}

__global__ void __launch_bounds__(TPB, 10)   // ~51-reg cap, target 10+ CTAs/SM
qmv4_kernel(const float* __restrict__ x,
            const int*   __restrict__ qw,
            const float* __restrict__ scales,
            const float* __restrict__ zeros,
            const float* __restrict__ bias,
            float* __restrict__ out)
{
    const int tid = threadIdx.x;
    const int ob  = blockIdx.x * OBLK;   // output base of this block
    const int rz  = blockIdx.y * RW;     // word-row base of this k-split

    // Weight ring: DEPTH stages x TPB threads x 16B. Thread tid stages and
    // consumes ONLY its own 16B slot -> no per-stage __syncthreads needed.
    __shared__ __align__(16) int4  ws[DEPTH][TPB];
    __shared__ __align__(16) float xs[RW * 8];   // x chunk (64 floats)

    const int stride = OUT / 4;          // int4 elements per word-row
    const int4* qp = reinterpret_cast<const int4*>(qw)
                     + (size_t)rz * stride + (ob >> 2) + tid;

    unsigned my_slot[DEPTH];
    {
        unsigned base;
        asm("{ .reg .u64 t; cvta.to.shared.u64 t, %1; cvt.u32.u64 %0, t; }"
            : "=r"(base) : "l"(&ws[0][tid]));
        #pragma unroll
        for (int p = 0; p < DEPTH; ++p)
            my_slot[p] = base + p * (TPB * 16);
    }

    // Prologue: fill the pipeline (DEPTH rows in flight, no regs held)
    #pragma unroll
    for (int p = 0; p < DEPTH; ++p) {
        CP_ASYNC16(my_slot[p], qp + (size_t)p * stride);
        CP_COMMIT();
    }

    // Stage x while weights fly. One barrier total (for cross-thread xs reads).
    if (tid < (RW * 8) / 4) {
        reinterpret_cast<float4*>(xs)[tid] =
            reinterpret_cast<const float4*>(x + rz * 8)[tid];
    }
    __syncthreads();

    unsigned long long accp0 = 0ull, accp1 = 0ull, accp2 = 0ull, accp3 = 0ull;
    const unsigned long long* xsp = reinterpret_cast<const unsigned long long*>(xs);

    #pragma unroll
    for (int r = 0; r < RW; ++r) {
        const int slot = r % DEPTH;
        CP_WAIT(DEPTH - 1);              // row r resident (self-visible)
        int4 q = ws[slot][tid];          // LDS.128, conflict-free
        if (r + DEPTH < RW) {            // refill the slot just vacated
            CP_ASYNC16(my_slot[slot], qp + (size_t)(r + DEPTH) * stride);
        }
        CP_COMMIT();                     // keep group count in lockstep

        unsigned long long xp[4];        // 4 packed {x_even,x_odd} pairs, row r
        xp[0] = xsp[r * 4 + 0];
        xp[1] = xsp[r * 4 + 1];
        xp[2] = xsp[r * 4 + 2];
        xp[3] = xsp[r * 4 + 3];
        proc_word2((unsigned)q.x, accp0, xp);
        proc_word2((unsigned)q.y, accp1, xp);
        proc_word2((unsigned)q.z, accp2, xp);
        proc_word2((unsigned)q.w, accp3, xp);
    }

    // Per-warp xsum after the loop: no barrier, no broadcast wait.
    const int lane = tid & 31;
    float2 xv = reinterpret_cast<const float2*>(xs)[lane];
    float xsum = xv.x + xv.y;
    #pragma unroll
    for (int off = 16; off; off >>= 1)
        xsum += __shfl_xor_sync(0xffffffffu, xsum, off);

    float acc0 = unpack_add(accp0);
    float acc1 = unpack_add(accp1);
    float acc2 = unpack_add(accp2);
    float acc3 = unpack_add(accp3);

    const int o = ob + tid * OPT;
    float4 sc = *reinterpret_cast<const float4*>(scales + o);
    float4 zr = *reinterpret_cast<const float4*>(zeros  + o);

    // acc accumulated x*(128+n); subtract 128*sum(x over range) exactly.
    float r0 = sc.x * (acc0 - 128.f * xsum) - zr.x * xsum;
    float r1 = sc.y * (acc1 - 128.f * xsum) - zr.y * xsum;
    float r2 = sc.z * (acc2 - 128.f * xsum) - zr.z * xsum;
    float r3 = sc.w * (acc3 - 128.f * xsum) - zr.w * xsum;

    if (blockIdx.y == 0) {   // bias added exactly once
        float4 bi = *reinterpret_cast<const float4*>(bias + o);
        r0 += bi.x; r1 += bi.y; r2 += bi.z; r3 += bi.w;
    }

    atomicAdd(out + o + 0, r0);
    atomicAdd(out + o + 1, r1);
    atomicAdd(out + o + 2, r2);
    atomicAdd(out + o + 3, r3);
}

extern "C" void kernel_launch(void* const* d_in, const int* in_sizes, int n_in,
                              void* d_out, int out_size)
{
    const float* x      = (const float*)d_in[0];
    const int*   qw     = (const int*)  d_in[1];
    const float* scales = (const float*)d_in[2];
    const float* zeros  = (const float*)d_in[3];
    const float* bias   = (const float*)d_in[4];
    float* out = (float*)d_out;

    // Zero the split-K accumulation target every launch (graph-replay idempotent)
    cudaMemsetAsync(out, 0, OUT * sizeof(float), 0);

    dim3 grid(OTILES, KSPLIT);
    qmv4_kernel<<<grid, TPB>>>(x, qw, scales, zeros, bias, out);
}

// round 15
// speedup vs baseline: 1.0928x; 1.0928x over previous
#include <cuda_runtime.h>

// Problem constants (fixed shapes from reference setup_inputs)
#define IN      8192
#define OUT     8192
#define RWORDS  1024            // IN * 4 / 32 packed int32 rows
#define KSPLIT  128             // split-K factor
#define RW      (RWORDS / KSPLIT)   // 8 word-rows per block
#define TPB     128
#define OPT     4               // outputs per thread (one 16B slot)
#define OBLK    (TPB * OPT)     // 512 outputs per block
#define OTILES  (OUT / OBLK)    // 16

// cp.async 16B: global -> shared, bypassing registers.
#define CP_ASYNC16(smem_u32, gptr)                                        \
    asm volatile("cp.async.cg.shared.global [%0], [%1], 16;"              \
                 :: "r"(smem_u32), "l"(gptr))
#define CP_COMMIT() asm volatile("cp.async.commit_group;")
#define CP_WAIT0()  asm volatile("cp.async.wait_group 0;")

// PRMT exponent-splice: bytes [0,0,n,0x43] -> exactly 128.0f + n (one ALU op)
__device__ __forceinline__ unsigned nib2f_bits(unsigned v, unsigned sel) {
    unsigned r;
    asm("prmt.b32 %0, %1, %2, %3;" : "=r"(r) : "r"(v), "n"(0x43000000u), "r"(sel));
    return r;
}

// Packed f32x2 FMA: accp += {lo,hi} * xp   (exact fp32 math, 2 MACs/inst)
__device__ __forceinline__ void fma2(unsigned long long& accp,
                                     unsigned lo, unsigned hi,
                                     unsigned long long xp) {
    unsigned long long wp;
    asm("mov.b64 %0, {%1,%2};" : "=l"(wp) : "r"(lo), "r"(hi));
    asm("fma.rn.f32x2 %0, %1, %2, %3;" : "=l"(accp) : "l"(wp), "l"(xp), "l"(accp));
}

// One packed word: 8 nibbles as 4 even/odd k-pairs into an f32x2 accumulator.
__device__ __forceinline__ void proc_word2(unsigned qword, unsigned long long& accp,
                                           const unsigned long long* xp) {
    unsigned wl = qword & 0x0F0F0F0Fu;
    unsigned wh = (qword >> 4) & 0x0F0F0F0Fu;
    fma2(accp, nib2f_bits(wl, 0x7044u), nib2f_bits(wh, 0x7044u), xp[0]);
    fma2(accp, nib2f_bits(wl, 0x7144u), nib2f_bits(wh, 0x7144u), xp[1]);
    fma2(accp, nib2f_bits(wl, 0x7244u), nib2f_bits(wh, 0x7244u), xp[2]);
    fma2(accp, nib2f_bits(wl, 0x7344u), nib2f_bits(wh, 0x7344u), xp[3]);
}

__device__ __forceinline__ float unpack_add(unsigned long long p) {
    unsigned lo, hi;
    asm("mov.b64 {%0,%1}, %2;" : "=r"(lo), "=r"(hi) : "l"(p));
    return __uint_as_float(lo) + __uint_as_float(hi);
}

__global__ void __launch_bounds__(TPB, 12)
qmv4_kernel(const float* __restrict__ x,
            const int*   __restrict__ qw,
            const float* __restrict__ scales,
            const float* __restrict__ zeros,
            const float* __restrict__ bias,
            float* __restrict__ out)
{
    const int tid = threadIdx.x;
    const int ob  = blockIdx.x * OBLK;   // output base of this block
    const int rz  = blockIdx.y * RW;     // word-row base of this k-split

    // All RW rows staged at once: thread tid owns ws[r][tid] only.
    __shared__ __align__(16) int4  ws[RW][TPB];   // 16 KB
    __shared__ __align__(16) float xs[RW * 8];    // 256 B

    const int stride = OUT / 4;          // int4 elements per word-row
    const int4* qp = reinterpret_cast<const int4*>(qw)
                     + (size_t)rz * stride + (ob >> 2) + tid;

    // (1) Issue ALL weight loads in one group: 128 B/thread in flight,
    // one DRAM-latency exposure per CTA.
    unsigned slot0;
    asm("{ .reg .u64 t; cvta.to.shared.u64 t, %1; cvt.u32.u64 %0, t; }"
        : "=r"(slot0) : "l"(&ws[0][tid]));
    #pragma unroll
    for (int r = 0; r < RW; ++r)
        CP_ASYNC16(slot0 + r * (TPB * 16), qp + (size_t)r * stride);
    CP_COMMIT();

    // (2) Stage x while weights fly; barrier covers xs only.
    if (tid < (RW * 8) / 4) {
        reinterpret_cast<float4*>(xs)[tid] =
            reinterpret_cast<const float4*>(x + rz * 8)[tid];
    }
    __syncthreads();

    // (3) Single wait; self-slot reads need no further barrier.
    CP_WAIT0();

    unsigned long long accp0 = 0ull, accp1 = 0ull, accp2 = 0ull, accp3 = 0ull;
    const unsigned long long* xsp = reinterpret_cast<const unsigned long long*>(xs);

    #pragma unroll
    for (int r = 0; r < RW; ++r) {
        int4 q = ws[r][tid];             // LDS.128, conflict-free
        unsigned long long xp[4];        // 4 packed {x_even,x_odd} pairs, row r
        xp[0] = xsp[r * 4 + 0];
        xp[1] = xsp[r * 4 + 1];
        xp[2] = xsp[r * 4 + 2];
        xp[3] = xsp[r * 4 + 3];
        proc_word2((unsigned)q.x, accp0, xp);
        proc_word2((unsigned)q.y, accp1, xp);
        proc_word2((unsigned)q.z, accp2, xp);
        proc_word2((unsigned)q.w, accp3, xp);
    }

    // Per-warp xsum after the loop: no barrier, no broadcast wait.
    const int lane = tid & 31;
    float2 xv = reinterpret_cast<const float2*>(xs)[lane];
    float xsum = xv.x + xv.y;
    #pragma unroll
    for (int off = 16; off; off >>= 1)
        xsum += __shfl_xor_sync(0xffffffffu, xsum, off);

    float acc0 = unpack_add(accp0);
    float acc1 = unpack_add(accp1);
    float acc2 = unpack_add(accp2);
    float acc3 = unpack_add(accp3);

    const int o = ob + tid * OPT;
    float4 sc = *reinterpret_cast<const float4*>(scales + o);
    float4 zr = *reinterpret_cast<const float4*>(zeros  + o);

    // acc accumulated x*(128+n); subtract 128*sum(x over range) exactly.
    float r0 = sc.x * (acc0 - 128.f * xsum) - zr.x * xsum;
    float r1 = sc.y * (acc1 - 128.f * xsum) - zr.y * xsum;
    float r2 = sc.z * (acc2 - 128.f * xsum) - zr.z * xsum;
    float r3 = sc.w * (acc3 - 128.f * xsum) - zr.w * xsum;

    if (blockIdx.y == 0) {   // bias added exactly once
        float4 bi = *reinterpret_cast<const float4*>(bias + o);
        r0 += bi.x; r1 += bi.y; r2 += bi.z; r3 += bi.w;
    }

    atomicAdd(out + o + 0, r0);
    atomicAdd(out + o + 1, r1);
    atomicAdd(out + o + 2, r2);
    atomicAdd(out + o + 3, r3);
}

extern "C" void kernel_launch(void* const* d_in, const int* in_sizes, int n_in,
                              void* d_out, int out_size)
{
    const float* x      = (const float*)d_in[0];
    const int*   qw     = (const int*)  d_in[1];
    const float* scales = (const float*)d_in[2];
    const float* zeros  = (const float*)d_in[3];
    const float* bias   = (const float*)d_in[4];
    float* out = (float*)d_out;

    // Zero the split-K accumulation target every launch (graph-replay idempotent)
    cudaMemsetAsync(out, 0, OUT * sizeof(float), 0);

    dim3 grid(OTILES, KSPLIT);
    qmv4_kernel<<<grid, TPB>>>(x, qw, scales, zeros, bias, out);
}